// round 2
// baseline (speedup 1.0000x reference)
#include <cuda_runtime.h>
#include <cuda_bf16.h>

// NCEAverage: B=256, D=128, N=1e6, K1=2048, T=0.07, MOMENTUM=0.5
// Output: [ out_l(B*K1) | out_ab(B*K1) | new_memory_l(N*D) | new_memory_ab(N*D) ]

#define DIM 128
#define T_INV (1.0f / 0.07f)
#define NBLOCKS 1184          // 148 SMs * 8 blocks — one resident wave
#define BLK 256

// ---------------------------------------------------------------------------
// Fused copy + score. Roles interleaved by block parity so every wave mixes
// streaming copy traffic with random gather traffic (keeps DRAM saturated).
// ---------------------------------------------------------------------------
__global__ void __launch_bounds__(BLK) fused_kernel(
    const float* __restrict__ l, const float* __restrict__ ab,
    const int* __restrict__ idx,
    const float* __restrict__ mem_l, const float* __restrict__ mem_ab,
    float* __restrict__ out_l, float* __restrict__ out_ab,
    float* __restrict__ out_ml, float* __restrict__ out_mab,
    int B, int K1, long long ND)
{
    const int half = NBLOCKS / 2;

    if ((blockIdx.x & 1) == 0) {
        // ---- copy role: stream both 512 MB banks with float4 ----
        const long long M = ND >> 2;   // float4 count per bank
        long long i = (long long)(blockIdx.x >> 1) * BLK + threadIdx.x;
        const long long stride = (long long)half * BLK;
        const float4* __restrict__ s1 = (const float4*)mem_l;
        const float4* __restrict__ s2 = (const float4*)mem_ab;
        float4* __restrict__ d1 = (float4*)out_ml;
        float4* __restrict__ d2 = (float4*)out_mab;
        // unroll x2 for more loads in flight
        for (; i + stride < M; i += 2 * stride) {
            float4 a0 = s1[i];
            float4 b0 = s2[i];
            float4 a1 = s1[i + stride];
            float4 b1 = s2[i + stride];
            d1[i] = a0;  d2[i] = b0;
            d1[i + stride] = a1;  d2[i + stride] = b1;
        }
        if (i < M) { d1[i] = s1[i]; d2[i] = s2[i]; }
    } else {
        // ---- score role: one warp per (b,k); both banks' dots fused ----
        const int warp = threadIdx.x >> 5;
        const int lane = threadIdx.x & 31;
        const int ntask = B * K1;                 // 524288
        const int tstride = half * 8;             // warps in score role
        int task = (blockIdx.x >> 1) * 8 + warp;

        for (; task < ntask; task += tstride) {
            const int b = task / K1;
            const long long row = idx[task];

            const float4 wl  = ((const float4*)(mem_l  + row * DIM))[lane];
            const float4 wab = ((const float4*)(mem_ab + row * DIM))[lane];
            const float4 qab = ((const float4*)(ab + b * DIM))[lane];
            const float4 ql  = ((const float4*)(l  + b * DIM))[lane];

            float s_ab = wl.x * qab.x + wl.y * qab.y + wl.z * qab.z + wl.w * qab.w;
            float s_l  = wab.x * ql.x + wab.y * ql.y + wab.z * ql.z + wab.w * ql.w;

            #pragma unroll
            for (int off = 16; off; off >>= 1) {
                s_ab += __shfl_xor_sync(0xffffffffu, s_ab, off);
                s_l  += __shfl_xor_sync(0xffffffffu, s_l,  off);
            }
            if (lane == 0) {
                out_ab[task] = s_ab * T_INV;
                out_l[task]  = s_l  * T_INV;
            }
        }
    }
}

// ---------------------------------------------------------------------------
// EMA + L2-normalize + scatter. Runs after the copy (kernel boundary orders
// it). Duplicate-y resolution: last occurrence wins; dup check parallelized.
// ---------------------------------------------------------------------------
__global__ void __launch_bounds__(DIM) update_kernel(
    const float* __restrict__ l, const float* __restrict__ ab,
    const int* __restrict__ y,
    const float* __restrict__ mem_l, const float* __restrict__ mem_ab,
    float* __restrict__ out_ml, float* __restrict__ out_mab, int B)
{
    const int b   = blockIdx.x;
    const int tid = threadIdx.x;

    __shared__ int ys[1024];
    __shared__ int skip;
    for (int j = tid; j < B; j += DIM) ys[j] = y[j];
    if (tid == 0) skip = 0;
    __syncthreads();

    const int yy = ys[b];
    for (int j = b + 1 + tid; j < B; j += DIM)
        if (ys[j] == yy) skip = 1;   // benign race, all write 1
    __syncthreads();
    if (skip) return;

    const long long row = yy;
    const float vl  = 0.5f * mem_l [row * DIM + tid] + 0.5f * l [b * DIM + tid];
    const float vab = 0.5f * mem_ab[row * DIM + tid] + 0.5f * ab[b * DIM + tid];

    float sl = vl * vl, sab = vab * vab;
    #pragma unroll
    for (int off = 16; off; off >>= 1) {
        sl  += __shfl_xor_sync(0xffffffffu, sl,  off);
        sab += __shfl_xor_sync(0xffffffffu, sab, off);
    }
    __shared__ float wsl[4], wsab[4];
    const int w = tid >> 5, lane = tid & 31;
    if (lane == 0) { wsl[w] = sl; wsab[w] = sab; }
    __syncthreads();
    const float tsl  = wsl[0]  + wsl[1]  + wsl[2]  + wsl[3];
    const float tsab = wsab[0] + wsab[1] + wsab[2] + wsab[3];

    out_ml [row * DIM + tid] = vl  * rsqrtf(tsl);
    out_mab[row * DIM + tid] = vab * rsqrtf(tsab);
}

extern "C" void kernel_launch(void* const* d_in, const int* in_sizes, int n_in,
                              void* d_out, int out_size)
{
    const float* l      = (const float*)d_in[0];
    const float* ab     = (const float*)d_in[1];
    const int*   y      = (const int*)  d_in[2];
    const int*   idx    = (const int*)  d_in[3];
    const float* mem_l  = (const float*)d_in[4];
    const float* mem_ab = (const float*)d_in[5];

    const int       B  = in_sizes[2];
    const int       K1 = in_sizes[3] / B;
    const long long ND = (long long)in_sizes[4];
    const long long BK = (long long)B * K1;

    float* out = (float*)d_out;
    float* out_l   = out;
    float* out_ab  = out + BK;
    float* out_ml  = out + 2 * BK;
    float* out_mab = out + 2 * BK + ND;

    fused_kernel<<<NBLOCKS, BLK>>>(l, ab, idx, mem_l, mem_ab,
                                   out_l, out_ab, out_ml, out_mab,
                                   B, K1, ND);
    update_kernel<<<B, DIM>>>(l, ab, y, mem_l, mem_ab, out_ml, out_mab, B);
}

// round 3
// speedup vs baseline: 1.2628x; 1.2628x over previous
#include <cuda_runtime.h>
#include <cuda_bf16.h>

// NCEAverage: B=256, D=128, N=1e6, K1=2048, T=0.07, MOMENTUM=0.5
// Output: [ out_l(B*K1) | out_ab(B*K1) | new_memory_l(N*D) | new_memory_ab(N*D) ]

#define DIM 128
#define T_INV (1.0f / 0.07f)

// ---------------------------------------------------------------------------
// Score (+ folded row update). Runs AFTER both bank memcpys on the stream, so
// it may safely overwrite the B updated rows in the copied banks.
//   grid = (K1/8, B), block = 256 (8 warps, one (b,k) task per warp)
//   blocks with blockIdx.x == 0 additionally perform the EMA+normalize
//   scatter for their b (threads 0..127), after their score tasks.
// ---------------------------------------------------------------------------
__global__ void __launch_bounds__(256) score_update_kernel(
    const float* __restrict__ l, const float* __restrict__ ab,
    const int* __restrict__ y, const int* __restrict__ idx,
    const float* __restrict__ mem_l, const float* __restrict__ mem_ab,
    float* __restrict__ out_l, float* __restrict__ out_ab,
    float* __restrict__ out_ml, float* __restrict__ out_mab,
    int B, int K1)
{
    const int b   = blockIdx.y;
    const int tid = threadIdx.x;

    __shared__ float l_s[DIM];
    __shared__ float ab_s[DIM];
    if (tid < DIM)       l_s[tid]        = l[b * DIM + tid];
    else                 ab_s[tid - DIM] = ab[b * DIM + (tid - DIM)];
    __syncthreads();

    // ---- scoring: one warp per (b,k) ----
    const int warp = tid >> 5;
    const int lane = tid & 31;
    const int k    = blockIdx.x * 8 + warp;

    const long long row = idx[(long long)b * K1 + k];
    const float4 wl  = ((const float4*)(mem_l  + row * DIM))[lane];
    const float4 wab = ((const float4*)(mem_ab + row * DIM))[lane];
    const float4 qab = ((const float4*)ab_s)[lane];
    const float4 ql  = ((const float4*)l_s)[lane];

    float s_ab = wl.x * qab.x + wl.y * qab.y + wl.z * qab.z + wl.w * qab.w;
    float s_l  = wab.x * ql.x + wab.y * ql.y + wab.z * ql.z + wab.w * ql.w;

    #pragma unroll
    for (int off = 16; off; off >>= 1) {
        s_ab += __shfl_xor_sync(0xffffffffu, s_ab, off);
        s_l  += __shfl_xor_sync(0xffffffffu, s_l,  off);
    }
    if (lane == 0) {
        const long long o = (long long)b * K1 + k;
        out_ab[o] = s_ab * T_INV;
        out_l[o]  = s_l  * T_INV;
    }

    // ---- folded update: only blockIdx.x==0, threads 0..127 ----
    if (blockIdx.x != 0) return;

    __shared__ int skip;
    __shared__ int yy_s;
    if (tid == 0) { skip = 0; yy_s = y[b]; }
    __syncthreads();
    const int yy = yy_s;
    // last-occurrence-wins on duplicate y: skip if any later b' has same y
    for (int j = b + 1 + tid; j < B; j += 256)
        if (y[j] == yy) skip = 1;     // benign race; all write 1
    __syncthreads();
    if (skip || tid >= DIM) return;

    const long long r = yy;
    const float vl  = 0.5f * mem_l [r * DIM + tid] + 0.5f * l_s[tid];
    const float vab = 0.5f * mem_ab[r * DIM + tid] + 0.5f * ab_s[tid];

    float sl = vl * vl, sab = vab * vab;
    #pragma unroll
    for (int off = 16; off; off >>= 1) {
        sl  += __shfl_xor_sync(0xffffffffu, sl,  off);
        sab += __shfl_xor_sync(0xffffffffu, sab, off);
    }
    __shared__ float wsl[4], wsab[4];
    const int w = tid >> 5;
    if (lane == 0) { wsl[w] = sl; wsab[w] = sab; }
    __syncthreads();
    const float tsl  = wsl[0]  + wsl[1]  + wsl[2]  + wsl[3];
    const float tsab = wsab[0] + wsab[1] + wsab[2] + wsab[3];

    out_ml [r * DIM + tid] = vl  * rsqrtf(tsl);
    out_mab[r * DIM + tid] = vab * rsqrtf(tsab);
}

extern "C" void kernel_launch(void* const* d_in, const int* in_sizes, int n_in,
                              void* d_out, int out_size)
{
    const float* l      = (const float*)d_in[0];
    const float* ab     = (const float*)d_in[1];
    const int*   y      = (const int*)  d_in[2];
    const int*   idx    = (const int*)  d_in[3];
    const float* mem_l  = (const float*)d_in[4];
    const float* mem_ab = (const float*)d_in[5];

    const int       B  = in_sizes[2];
    const int       K1 = in_sizes[3] / B;
    const long long ND = (long long)in_sizes[4];
    const long long BK = (long long)B * K1;

    float* out = (float*)d_out;
    float* out_l   = out;
    float* out_ab  = out + BK;
    float* out_ml  = out + 2 * BK;
    float* out_mab = out + 2 * BK + ND;

    // 1) Passthrough copy of both banks (dominant cost; near-peak via memcpy).
    cudaMemcpyAsync(out_ml,  mem_l,  ND * sizeof(float), cudaMemcpyDeviceToDevice);
    cudaMemcpyAsync(out_mab, mem_ab, ND * sizeof(float), cudaMemcpyDeviceToDevice);

    // 2) Score + folded row update (ordered after the copies on this stream).
    dim3 sgrid(K1 / 8, B);
    score_update_kernel<<<sgrid, 256>>>(l, ab, y, idx, mem_l, mem_ab,
                                        out_l, out_ab, out_ml, out_mab, B, K1);
}

// round 4
// speedup vs baseline: 1.3552x; 1.0732x over previous
#include <cuda_runtime.h>
#include <cuda_bf16.h>

// NCEAverage: B=256, D=128, N=1e6, K1=2048, T=0.07, MOMENTUM=0.5
// Output: [ out_l(B*K1) | out_ab(B*K1) | new_memory_l(N*D) | new_memory_ab(N*D) ]
//
// Strategy: build a row->tasks CSR from idx (shared by both banks), then each
// bank is processed by ONE streaming pass that copies the bank AND computes
// all dot products for rows as they stream through registers. This removes
// the ~0.5 GB random-gather DRAM traffic of a separate score phase.

#define DIM      128
#define T_INV    (1.0f / 0.07f)
#define N_MAX    1048576
#define BK_MAX   524288
#define SCAN_B   1024

__device__ int g_count [N_MAX];
__device__ int g_offset[N_MAX];
__device__ int g_cursor[N_MAX];
__device__ int g_tasks [BK_MAX];
__device__ int g_bsum  [SCAN_B];

// ---------------- CSR build ----------------
__global__ void k_zero(int n) {
    for (int i = blockIdx.x * blockDim.x + threadIdx.x; i < n;
         i += gridDim.x * blockDim.x) g_count[i] = 0;
}

__global__ void k_hist(const int* __restrict__ idx, int bk) {
    for (int t = blockIdx.x * blockDim.x + threadIdx.x; t < bk;
         t += gridDim.x * blockDim.x) atomicAdd(&g_count[idx[t]], 1);
}

__global__ void k_scan1(int n) {            // per-block exclusive scan
    __shared__ int s[SCAN_B];
    const int tid = threadIdx.x;
    const int i   = blockIdx.x * SCAN_B + tid;
    const int v   = (i < n) ? g_count[i] : 0;
    s[tid] = v;
    __syncthreads();
    #pragma unroll
    for (int off = 1; off < SCAN_B; off <<= 1) {
        int t2 = (tid >= off) ? s[tid - off] : 0;
        __syncthreads();
        if (tid >= off) s[tid] += t2;
        __syncthreads();
    }
    const int incl = s[tid];
    if (i < n) g_offset[i] = incl - v;
    if (tid == SCAN_B - 1) g_bsum[blockIdx.x] = incl;
}

__global__ void k_scan2(int nb) {           // scan of block sums (single block)
    __shared__ int s[SCAN_B];
    const int tid = threadIdx.x;
    const int v   = (tid < nb) ? g_bsum[tid] : 0;
    s[tid] = v;
    __syncthreads();
    #pragma unroll
    for (int off = 1; off < SCAN_B; off <<= 1) {
        int t2 = (tid >= off) ? s[tid - off] : 0;
        __syncthreads();
        if (tid >= off) s[tid] += t2;
        __syncthreads();
    }
    if (tid < nb) g_bsum[tid] = s[tid] - v;  // exclusive
}

__global__ void k_scan3(int n) {            // add block base; init cursor
    const int i = blockIdx.x * SCAN_B + threadIdx.x;
    if (i < n) {
        const int o = g_offset[i] + g_bsum[blockIdx.x];
        g_offset[i] = o;
        g_cursor[i] = o;
    }
}

__global__ void k_scatter(const int* __restrict__ idx, int bk) {
    for (int t = blockIdx.x * blockDim.x + threadIdx.x; t < bk;
         t += gridDim.x * blockDim.x) {
        const int p = atomicAdd(&g_cursor[idx[t]], 1);
        g_tasks[p] = t;   // order within bucket irrelevant (distinct outputs)
    }
}

// ---------------- fused copy + score streaming pass ----------------
// One warp per row: copy 512B row, then dot vs query[b] for each task on it.
__global__ void __launch_bounds__(256) stream_score(
    const float4* __restrict__ bank, float4* __restrict__ outb,
    const float4* __restrict__ query, float* __restrict__ out_score,
    int Nrows, int K1)
{
    const int lane = threadIdx.x & 31;
    const int nw   = gridDim.x * (blockDim.x >> 5);
    int r          = blockIdx.x * (blockDim.x >> 5) + (threadIdx.x >> 5);

    if (r >= Nrows) return;
    float4 v = __ldcs(&bank[(long long)r * 32 + lane]);

    while (true) {
        const int rn = r + nw;
        float4 vn;
        if (rn < Nrows) vn = __ldcs(&bank[(long long)rn * 32 + lane]);  // prefetch

        __stcs(&outb[(long long)r * 32 + lane], v);
        const int cnt = g_count[r];
        if (cnt) {
            const int off = g_offset[r];
            for (int j = 0; j < cnt; ++j) {
                const int task = g_tasks[off + j];
                const int b    = task / K1;
                const float4 q = query[b * 32 + lane];
                float s = v.x * q.x + v.y * q.y + v.z * q.z + v.w * q.w;
                #pragma unroll
                for (int o = 16; o; o >>= 1) s += __shfl_xor_sync(0xffffffffu, s, o);
                if (lane == 0) out_score[task] = s * T_INV;
            }
        }
        if (rn >= Nrows) break;
        r = rn;
        v = vn;
    }
}

// ---------------- EMA + normalize + scatter (last-occurrence wins) ----------
__global__ void __launch_bounds__(DIM) update_kernel(
    const float* __restrict__ l, const float* __restrict__ ab,
    const int* __restrict__ y,
    const float* __restrict__ mem_l, const float* __restrict__ mem_ab,
    float* __restrict__ out_ml, float* __restrict__ out_mab, int B)
{
    const int b   = blockIdx.x;
    const int tid = threadIdx.x;

    __shared__ int skip;
    __shared__ int yy_s;
    if (tid == 0) { skip = 0; yy_s = y[b]; }
    __syncthreads();
    const int yy = yy_s;
    for (int j = b + 1 + tid; j < B; j += DIM)
        if (y[j] == yy) skip = 1;     // benign race
    __syncthreads();
    if (skip) return;

    const long long r = yy;
    const float vl  = 0.5f * mem_l [r * DIM + tid] + 0.5f * l [b * DIM + tid];
    const float vab = 0.5f * mem_ab[r * DIM + tid] + 0.5f * ab[b * DIM + tid];

    float sl = vl * vl, sab = vab * vab;
    #pragma unroll
    for (int off = 16; off; off >>= 1) {
        sl  += __shfl_xor_sync(0xffffffffu, sl,  off);
        sab += __shfl_xor_sync(0xffffffffu, sab, off);
    }
    __shared__ float wsl[4], wsab[4];
    const int w = tid >> 5, lane = tid & 31;
    if (lane == 0) { wsl[w] = sl; wsab[w] = sab; }
    __syncthreads();
    const float tsl  = wsl[0]  + wsl[1]  + wsl[2]  + wsl[3];
    const float tsab = wsab[0] + wsab[1] + wsab[2] + wsab[3];

    out_ml [r * DIM + tid] = vl  * rsqrtf(tsl);
    out_mab[r * DIM + tid] = vab * rsqrtf(tsab);
}

extern "C" void kernel_launch(void* const* d_in, const int* in_sizes, int n_in,
                              void* d_out, int out_size)
{
    const float* l      = (const float*)d_in[0];
    const float* ab     = (const float*)d_in[1];
    const int*   y      = (const int*)  d_in[2];
    const int*   idx    = (const int*)  d_in[3];
    const float* mem_l  = (const float*)d_in[4];
    const float* mem_ab = (const float*)d_in[5];

    const int       B     = in_sizes[2];
    const int       BK    = in_sizes[3];
    const int       K1    = BK / B;
    const long long ND    = (long long)in_sizes[4];
    const int       Nrows = (int)(ND / DIM);

    float* out = (float*)d_out;
    float* out_l   = out;
    float* out_ab  = out + BK;
    float* out_ml  = out + 2LL * BK;
    float* out_mab = out + 2LL * BK + ND;

    // ---- CSR build (row -> tasks), shared by both banks ----
    const int nb = (Nrows + SCAN_B - 1) / SCAN_B;
    k_zero   <<<512, 1024>>>(Nrows);
    k_hist   <<<512, 1024>>>(idx, BK);
    k_scan1  <<<nb, SCAN_B>>>(Nrows);
    k_scan2  <<<1,  SCAN_B>>>(nb);
    k_scan3  <<<nb, SCAN_B>>>(Nrows);
    k_scatter<<<512, 1024>>>(idx, BK);

    // ---- fused streaming passes: copy bank + score its tasks ----
    const int sblocks = 148 * 8;
    // bank = mem_l : dot(mem_l[row], ab[b]) -> out_ab
    stream_score<<<sblocks, 256>>>((const float4*)mem_l,  (float4*)out_ml,
                                   (const float4*)ab, out_ab, Nrows, K1);
    // bank = mem_ab: dot(mem_ab[row], l[b]) -> out_l
    stream_score<<<sblocks, 256>>>((const float4*)mem_ab, (float4*)out_mab,
                                   (const float4*)l,  out_l,  Nrows, K1);

    // ---- row updates (after copies; reads OLD memory from inputs) ----
    update_kernel<<<B, DIM>>>(l, ab, y, mem_l, mem_ab, out_ml, out_mab, B);
}